// round 3
// baseline (speedup 1.0000x reference)
#include <cuda_runtime.h>
#include <cuda_fp16.h>
#include <math.h>

#define N_RAYS    65536
#define N_SAMPLES 192
#define NGROUPS   6
#define EPSV      1e-10f

// Output layout: flattened tuple concat
#define OFF_RGB   0
#define OFF_DENS  (N_RAYS * 3)
#define OFF_ACC   (N_RAYS * 194)
#define OFF_W     (N_RAYS * 195)
#define OFF_DEPTH (N_RAYS * 387)

__device__ __forceinline__ float fast_sigmoid(float x) {
    float t;
    asm("tanh.approx.f32 %0, %1;" : "=f"(t) : "f"(x * 0.5f));
    return fmaf(t, 0.5f, 0.5f);
}

__global__ __launch_bounds__(256, 6)
void nerf_volrender_kernel(const float4* __restrict__ raw4,
                           const float*  __restrict__ z_vals,
                           const float*  __restrict__ rays_d,
                           float*        __restrict__ out)
{
    const unsigned FULL = 0xFFFFFFFFu;
    int gwarp = (blockIdx.x * blockDim.x + threadIdx.x) >> 5;
    int lane  = threadIdx.x & 31;
    if (gwarp >= N_RAYS) return;
    const int r = gwarp;

    float dx = __ldg(&rays_d[r * 3 + 0]);
    float dy = __ldg(&rays_d[r * 3 + 1]);
    float dz = __ldg(&rays_d[r * 3 + 2]);
    float dnorm = sqrtf(dx * dx + dy * dy + dz * dz);

    // coalesced streaming z loads: sample s = 32*j + lane
    float zv[NGROUPS];
    const int zbase = r * N_SAMPLES;
    #pragma unroll
    for (int j = 0; j < NGROUPS; j++)
        zv[j] = __ldcs(&z_vals[zbase + (j << 5) + lane]);

    // ---- phase 1: loads + density + sigmoids (fp16-packed) + group scans ----
    float  p[NGROUPS];            // inclusive within-group product of t
    __half2 hrg[NGROUPS];         // packed (sigmoid r, sigmoid g)
    __half2 hb[NGROUPS / 2];      // packed sigmoid b for group pairs (2j, 2j+1)
    float bb_prev = 0.0f;

    #pragma unroll
    for (int j = 0; j < NGROUPS; j++) {
        const int s = (j << 5) + lane;
        float4 rv = __ldcs(&raw4[zbase + s]);

        // z[s+1]: shuffle within group; lane 31 takes next group's lane 0
        float zn = __shfl_down_sync(FULL, zv[j], 1);
        if (j < NGROUPS - 1) {
            float znext0 = __shfl_sync(FULL, zv[j + 1], 0);
            if (lane == 31) zn = znext0;
        }
        float dist = fabsf(zn - zv[j]) * dnorm;

        float dens = fmaxf(rv.w, 0.0f);
        if (s < N_SAMPLES - 1)
            __stcs(&out[OFF_DENS + r * (N_SAMPLES - 1) + s], dens);

        bool last = (s == N_SAMPLES - 1);
        float alpha = last ? 1.0f : (1.0f - __expf(-dens * dist));
        float t = (1.0f + EPSV) - alpha;

        // sigmoids now, pack to fp16 to cut live registers across phases
        float rr = fast_sigmoid(rv.x);
        float gg = fast_sigmoid(rv.y);
        float bbv = fast_sigmoid(rv.z);
        hrg[j] = __halves2half2(__float2half_rn(rr), __float2half_rn(gg));
        if (j & 1)
            hb[j >> 1] = __halves2half2(__float2half_rn(bb_prev), __float2half_rn(bbv));
        else
            bb_prev = bbv;

        // multiplicative inclusive warp scan of t
        float pp = t;
        #pragma unroll
        for (int d = 1; d < 32; d <<= 1) {
            float o = __shfl_up_sync(FULL, pp, d);
            if (lane >= d) pp *= o;
        }
        p[j] = pp;
    }

    // ---- phase 2: combine groups; w = (1+eps)*trans - incl (exact) ----
    float off = 1.0f;
    float sr = 0.f, sg = 0.f, sb = 0.f, sw = 0.f, sd = 0.f;
    #pragma unroll
    for (int j = 0; j < NGROUPS; j++) {
        const int s = (j << 5) + lane;

        float excl = __shfl_up_sync(FULL, p[j], 1);
        if (lane == 0) excl = 1.0f;
        float trans = off * excl;                    // exclusive cumprod
        float incl  = off * p[j];                    // inclusive cumprod
        float w = fmaf(EPSV, trans, trans - incl);   // alpha * trans, exact

        __stcs(&out[OFF_W + r * N_SAMPLES + s], w);

        float rr = __low2float(hrg[j]);
        float gg = __high2float(hrg[j]);
        float bbv = (j & 1) ? __high2float(hb[j >> 1]) : __low2float(hb[j >> 1]);
        sr += w * rr;
        sg += w * gg;
        sb += w * bbv;
        sw += w;
        sd += w * zv[j];

        off *= __shfl_sync(FULL, p[j], 31);
    }

    // ---- warp reduction of the 5 accumulators ----
    #pragma unroll
    for (int d = 16; d > 0; d >>= 1) {
        sr += __shfl_down_sync(FULL, sr, d);
        sg += __shfl_down_sync(FULL, sg, d);
        sb += __shfl_down_sync(FULL, sb, d);
        sw += __shfl_down_sync(FULL, sw, d);
        sd += __shfl_down_sync(FULL, sd, d);
    }
    if (lane == 0) {
        out[OFF_RGB + r * 3 + 0] = sr;
        out[OFF_RGB + r * 3 + 1] = sg;
        out[OFF_RGB + r * 3 + 2] = sb;
        out[OFF_ACC   + r] = sw;
        out[OFF_DEPTH + r] = sd;
    }
}

extern "C" void kernel_launch(void* const* d_in, const int* in_sizes, int n_in,
                              void* d_out, int out_size)
{
    const float4* raw4   = (const float4*)d_in[0];
    const float*  z_vals = (const float*)d_in[1];
    const float*  rays_d = (const float*)d_in[2];
    float* out = (float*)d_out;

    const int threads = 256;
    const int blocks  = (N_RAYS * 32) / threads;
    nerf_volrender_kernel<<<blocks, threads>>>(raw4, z_vals, rays_d, out);
}

// round 4
// speedup vs baseline: 1.1314x; 1.1314x over previous
#include <cuda_runtime.h>
#include <math.h>

#define N_RAYS    65536
#define N_SAMPLES 192
#define NGROUPS   6
#define EPSV      1e-10f

// Output layout: flattened tuple concat
#define OFF_RGB   0
#define OFF_DENS  (N_RAYS * 3)
#define OFF_ACC   (N_RAYS * 194)
#define OFF_W     (N_RAYS * 195)
#define OFF_DEPTH (N_RAYS * 387)

__device__ __forceinline__ float fast_sigmoid(float x) {
    float t;
    asm("tanh.approx.f32 %0, %1;" : "=f"(t) : "f"(x * 0.5f));
    return fmaf(t, 0.5f, 0.5f);
}

__global__ __launch_bounds__(256, 6)
void nerf_volrender_kernel(const float4* __restrict__ raw4,
                           const float*  __restrict__ z_vals,
                           const float*  __restrict__ rays_d,
                           float*        __restrict__ out)
{
    const unsigned FULL = 0xFFFFFFFFu;
    int gwarp = (blockIdx.x * blockDim.x + threadIdx.x) >> 5;
    int lane  = threadIdx.x & 31;
    if (gwarp >= N_RAYS) return;
    const int r = gwarp;

    float dx = __ldg(&rays_d[r * 3 + 0]);
    float dy = __ldg(&rays_d[r * 3 + 1]);
    float dz = __ldg(&rays_d[r * 3 + 2]);
    float dnorm = sqrtf(dx * dx + dy * dy + dz * dz);

    const int zbase = r * N_SAMPLES;

    // front batch: all 6 z loads + first 2 raw loads (8 LDGs in flight)
    float zv[NGROUPS];
    #pragma unroll
    for (int j = 0; j < NGROUPS; j++)
        zv[j] = __ldcs(&z_vals[zbase + (j << 5) + lane]);

    float4 rbuf[NGROUPS];           // fully unrolled; liveness spans ~2 groups
    rbuf[0] = __ldcs(&raw4[zbase + 0 * 32 + lane]);
    rbuf[1] = __ldcs(&raw4[zbase + 1 * 32 + lane]);

    float off = 1.0f;
    float sr = 0.f, sg = 0.f, sb = 0.f, sw = 0.f, sd = 0.f;

    #pragma unroll
    for (int j = 0; j < NGROUPS; j++) {
        // prefetch raw for group j+2 (keeps one LDG.128 in flight ahead)
        if (j + 2 < NGROUPS)
            rbuf[j + 2] = __ldcs(&raw4[zbase + ((j + 2) << 5) + lane]);

        const int s = (j << 5) + lane;
        const float4 rv = rbuf[j];

        // z[s+1]: shuffle within group; lane 31 takes next group's lane 0
        float zn = __shfl_down_sync(FULL, zv[j], 1);
        if (j < NGROUPS - 1) {
            float znext0 = __shfl_sync(FULL, zv[j + 1], 0);
            if (lane == 31) zn = znext0;
        }
        float dist = fabsf(zn - zv[j]) * dnorm;

        float dens = fmaxf(rv.w, 0.0f);
        if (s < N_SAMPLES - 1)
            __stcs(&out[OFF_DENS + r * (N_SAMPLES - 1) + s], dens);

        bool last = (s == N_SAMPLES - 1);
        float alpha = last ? 1.0f : (1.0f - __expf(-dens * dist));
        float t = (1.0f + EPSV) - alpha;

        // multiplicative inclusive warp scan of t (independent of `off`)
        float pp = t;
        #pragma unroll
        for (int d = 1; d < 32; d <<= 1) {
            float o = __shfl_up_sync(FULL, pp, d);
            if (lane >= d) pp *= o;
        }

        float excl = __shfl_up_sync(FULL, pp, 1);
        if (lane == 0) excl = 1.0f;
        float trans = off * excl;                    // exclusive cumprod
        float incl  = off * pp;                      // inclusive cumprod
        float w = fmaf(EPSV, trans, trans - incl);   // alpha * trans, exact

        __stcs(&out[OFF_W + r * N_SAMPLES + s], w);

        sr += w * fast_sigmoid(rv.x);
        sg += w * fast_sigmoid(rv.y);
        sb += w * fast_sigmoid(rv.z);
        sw += w;
        sd += w * zv[j];

        off *= __shfl_sync(FULL, pp, 31);
    }

    // warp reduction of the 5 accumulators
    #pragma unroll
    for (int d = 16; d > 0; d >>= 1) {
        sr += __shfl_down_sync(FULL, sr, d);
        sg += __shfl_down_sync(FULL, sg, d);
        sb += __shfl_down_sync(FULL, sb, d);
        sw += __shfl_down_sync(FULL, sw, d);
        sd += __shfl_down_sync(FULL, sd, d);
    }
    if (lane == 0) {
        out[OFF_RGB + r * 3 + 0] = sr;
        out[OFF_RGB + r * 3 + 1] = sg;
        out[OFF_RGB + r * 3 + 2] = sb;
        out[OFF_ACC   + r] = sw;
        out[OFF_DEPTH + r] = sd;
    }
}

extern "C" void kernel_launch(void* const* d_in, const int* in_sizes, int n_in,
                              void* d_out, int out_size)
{
    const float4* raw4   = (const float4*)d_in[0];
    const float*  z_vals = (const float*)d_in[1];
    const float*  rays_d = (const float*)d_in[2];
    float* out = (float*)d_out;

    const int threads = 256;
    const int blocks  = (N_RAYS * 32) / threads;
    nerf_volrender_kernel<<<blocks, threads>>>(raw4, z_vals, rays_d, out);
}